// round 16
// baseline (speedup 1.0000x reference)
#include <cuda_runtime.h>
#include <cstdint>

// out[o,i,h,w] = sum_k weights[o,i,k] * x[k,h,w]
// OUT_CH = IN_CH = 2048, x is 3x3x3, output is (2048,2048,3,3) fp32.
//
// FINAL — at the empirical DRAM write ceiling (~4.9 TB/s, confirmed
// path-independent across TMA-only / STG-only / mixed drains, R10-R13;
// occupancy/pipelining insensitive, R7-R9, R14). Steady-state traffic is
// writes-only (weights L2-resident under graph replay), so kernel time is
// pinned at ~29us = 151MB / 4.9TB/s.
//
// Structure: double-buffered streaming kernel. Each block covers 1024 (o,i)
// pairs in two 512-pair tiles. Per tile: each thread computes 2 pairs
// (18 floats), stages into that tile's smem buffer (conflict-free STS.64),
// and each warp drains its contiguous 2304B slice with its own 1D TMA bulk
// store. Tile1's compute overlaps tile0's TMA flight; one wait_group 0 at
// the end covers both commits.

__global__ void __launch_bounds__(256, 5) gf_layer_kernel(
    const float* __restrict__ x,
    const float* __restrict__ w,
    float* __restrict__ out) {
    __shared__ alignas(128) float sout[2][256 * 18];  // 2 x 18 KB buffers
    __shared__ alignas(16) float xs[28];

    const int tid = threadIdx.x;
    if (tid < 27) xs[tid] = x[tid];
    __syncthreads();

    const int wid = tid >> 5;
    const int lid = tid & 31;
    const long long block_pair0 = (long long)blockIdx.x * 1024;

#pragma unroll
    for (int t = 0; t < 2; t++) {
        // First (o,i) pair for this thread in tile t.
        const long long p = block_pair0 + t * 512 + tid * 2;

        // 6 contiguous weights (2 pairs x 3 coeffs); byte offset p*12 is
        // 24B-aligned -> 3x float2 loads. w (50MB) stays L2-resident.
        const float2* __restrict__ w2 =
            reinterpret_cast<const float2*>(w + p * 3);
        const float2 wa = w2[0];
        const float2 wb = w2[1];
        const float2 wc = w2[2];
        const float wv[6] = {wa.x, wa.y, wb.x, wb.y, wc.x, wc.y};

        float o[18];
#pragma unroll
        for (int pp = 0; pp < 2; pp++) {
            const float c0 = wv[pp * 3 + 0];
            const float c1 = wv[pp * 3 + 1];
            const float c2 = wv[pp * 3 + 2];
#pragma unroll
            for (int j = 0; j < 9; j++) {
                o[pp * 9 + j] =
                    fmaf(c0, xs[j], fmaf(c1, xs[9 + j], c2 * xs[18 + j]));
            }
        }

        // Stage to smem as float2: thread stride = 18 floats = 72B. STS.64
        // phase = 16 lanes; banks (18*l) mod 32 are 16 distinct even values
        // -> conflict-free.
        float2* __restrict__ s2 =
            reinterpret_cast<float2*>(&sout[t][0] + tid * 18);
#pragma unroll
        for (int i = 0; i < 9; i++) {
            s2[i] = make_float2(o[2 * i], o[2 * i + 1]);
        }

        __syncwarp();

        // Per-warp TMA drain: warp wid owns 2304 contiguous bytes of tile t.
        if (lid == 0) {
            const float* ssrc = &sout[t][0] + wid * (32 * 18);
            uint32_t saddr;
            asm("{ .reg .u64 q; cvta.to.shared.u64 q, %1; cvt.u32.u64 %0, q; }"
                : "=r"(saddr) : "l"(ssrc));
            float* gdst =
                out + (block_pair0 + t * 512) * 9 + wid * (32 * 18);
            asm volatile("fence.proxy.async.shared::cta;" ::: "memory");
            asm volatile(
                "cp.async.bulk.global.shared::cta.bulk_group [%0], [%1], %2;"
                :: "l"(gdst), "r"(saddr), "r"(32 * 18 * 4) : "memory");
            asm volatile("cp.async.bulk.commit_group;" ::: "memory");
        }
    }

    // Single wait for both in-flight bulk stores before smem teardown.
    if (lid == 0) {
        asm volatile("cp.async.bulk.wait_group 0;" ::: "memory");
    }
}

extern "C" void kernel_launch(void* const* d_in, const int* in_sizes, int n_in,
                              void* d_out, int out_size) {
    // Inputs: x (27 elems), weights (2048*2048*3). Identify x by element count.
    const float* x;
    const float* w;
    long long w_elems;
    if (in_sizes[0] == 27) {
        x = (const float*)d_in[0];
        w = (const float*)d_in[1];
        w_elems = in_sizes[1];
    } else {
        x = (const float*)d_in[1];
        w = (const float*)d_in[0];
        w_elems = in_sizes[0];
    }

    float* out = (float*)d_out;

    const long long total_pairs = w_elems / 3;    // (o,i) pairs = 4,194,304
    const long long pairs_per_block = 1024;       // 2 tiles x 512
    const int blocks = (int)(total_pairs / pairs_per_block);  // 4096, exact

    gf_layer_kernel<<<blocks, 256>>>(x, w, out);
}

// round 17
// speedup vs baseline: 1.0072x; 1.0072x over previous
#include <cuda_runtime.h>
#include <cstdint>

// out[o,i,h,w] = sum_k weights[o,i,k] * x[k,h,w]
// OUT_CH = IN_CH = 2048, x is 3x3x3, output is (2048,2048,3,3) fp32.
//
// FINAL — at the empirical DRAM write ceiling (~4.9 TB/s, confirmed
// path-independent across TMA-only / STG-only / mixed drains, R10-R13;
// occupancy/pipelining insensitive, R7-R9, R14). Steady-state traffic is
// writes-only (weights L2-resident under graph replay), so kernel time is
// pinned at ~29us = 151MB / 4.9TB/s; bench adds ~6us fixed replay overhead.
//
// Structure: double-buffered streaming kernel. Each block covers 1024 (o,i)
// pairs in two 512-pair tiles. Per tile: each thread computes 2 pairs
// (18 floats), stages into that tile's smem buffer (conflict-free STS.64),
// and each warp drains its contiguous 2304B slice with its own 1D TMA bulk
// store. Tile1's compute overlaps tile0's TMA flight; one wait_group 0 at
// the end covers both commits.

__global__ void __launch_bounds__(256, 5) gf_layer_kernel(
    const float* __restrict__ x,
    const float* __restrict__ w,
    float* __restrict__ out) {
    __shared__ alignas(128) float sout[2][256 * 18];  // 2 x 18 KB buffers
    __shared__ alignas(16) float xs[28];

    const int tid = threadIdx.x;
    if (tid < 27) xs[tid] = x[tid];
    __syncthreads();

    const int wid = tid >> 5;
    const int lid = tid & 31;
    const long long block_pair0 = (long long)blockIdx.x * 1024;

#pragma unroll
    for (int t = 0; t < 2; t++) {
        // First (o,i) pair for this thread in tile t.
        const long long p = block_pair0 + t * 512 + tid * 2;

        // 6 contiguous weights (2 pairs x 3 coeffs); byte offset p*12 is
        // 24B-aligned -> 3x float2 loads. w (50MB) stays L2-resident.
        const float2* __restrict__ w2 =
            reinterpret_cast<const float2*>(w + p * 3);
        const float2 wa = w2[0];
        const float2 wb = w2[1];
        const float2 wc = w2[2];
        const float wv[6] = {wa.x, wa.y, wb.x, wb.y, wc.x, wc.y};

        float o[18];
#pragma unroll
        for (int pp = 0; pp < 2; pp++) {
            const float c0 = wv[pp * 3 + 0];
            const float c1 = wv[pp * 3 + 1];
            const float c2 = wv[pp * 3 + 2];
#pragma unroll
            for (int j = 0; j < 9; j++) {
                o[pp * 9 + j] =
                    fmaf(c0, xs[j], fmaf(c1, xs[9 + j], c2 * xs[18 + j]));
            }
        }

        // Stage to smem as float2: thread stride = 18 floats = 72B. STS.64
        // phase = 16 lanes; banks (18*l) mod 32 are 16 distinct even values
        // -> conflict-free.
        float2* __restrict__ s2 =
            reinterpret_cast<float2*>(&sout[t][0] + tid * 18);
#pragma unroll
        for (int i = 0; i < 9; i++) {
            s2[i] = make_float2(o[2 * i], o[2 * i + 1]);
        }

        __syncwarp();

        // Per-warp TMA drain: warp wid owns 2304 contiguous bytes of tile t.
        if (lid == 0) {
            const float* ssrc = &sout[t][0] + wid * (32 * 18);
            uint32_t saddr;
            asm("{ .reg .u64 q; cvta.to.shared.u64 q, %1; cvt.u32.u64 %0, q; }"
                : "=r"(saddr) : "l"(ssrc));
            float* gdst =
                out + (block_pair0 + t * 512) * 9 + wid * (32 * 18);
            asm volatile("fence.proxy.async.shared::cta;" ::: "memory");
            asm volatile(
                "cp.async.bulk.global.shared::cta.bulk_group [%0], [%1], %2;"
                :: "l"(gdst), "r"(saddr), "r"(32 * 18 * 4) : "memory");
            asm volatile("cp.async.bulk.commit_group;" ::: "memory");
        }
    }

    // Single wait for both in-flight bulk stores before smem teardown.
    if (lid == 0) {
        asm volatile("cp.async.bulk.wait_group 0;" ::: "memory");
    }
}

extern "C" void kernel_launch(void* const* d_in, const int* in_sizes, int n_in,
                              void* d_out, int out_size) {
    // Inputs: x (27 elems), weights (2048*2048*3). Identify x by element count.
    const float* x;
    const float* w;
    long long w_elems;
    if (in_sizes[0] == 27) {
        x = (const float*)d_in[0];
        w = (const float*)d_in[1];
        w_elems = in_sizes[1];
    } else {
        x = (const float*)d_in[1];
        w = (const float*)d_in[0];
        w_elems = in_sizes[0];
    }

    float* out = (float*)d_out;

    const long long total_pairs = w_elems / 3;    // (o,i) pairs = 4,194,304
    const long long pairs_per_block = 1024;       // 2 tiles x 512
    const int blocks = (int)(total_pairs / pairs_per_block);  // 4096, exact

    gf_layer_kernel<<<blocks, 256>>>(x, w, out);
}